// round 6
// baseline (speedup 1.0000x reference)
#include <cuda_runtime.h>
#include <cuda_fp16.h>
#include <stdint.h>

// SplineConv: N=100000, E=1.6M, DIM=2, K=5, deg-1 open spline, M_in=M_out=32, K_TOT=25.
#define MAXN 100000
#define MAXE 1600000
#define KTOT 25
#define KM   800   // KTOT*32 Z-channels per node
#define NBKT 1024  // sort buckets (col >> 7): 782 used for N=100000

// ---------------- device scratch (allocation-free) ----------------
__device__ __half g_Zh[(size_t)MAXN * KM];   // 160 MB fp16 Z[n, p]  (p = k*32+o)
__device__ __half g_Wh[KTOT * 32 * 32];      // [p=800][i=32] f16  (B operand)
__device__ uint4  g_edesc[MAXE];             // packed edges: {row, col|kidx<<20, fx, fy}
__device__ uint4  g_edesc2[MAXE];            // col-sorted descriptors
__device__ int    g_hist[NBKT];
__device__ int    g_off[NBKT];
__device__ float  g_deg[MAXN];
__device__ int    g_is64;

__device__ __forceinline__ uint32_t smem_u32(const void* p) {
    uint32_t a;
    asm("{ .reg .u64 t; cvta.to.shared.u64 t, %1; cvt.u32.u64 %0, t; }" : "=r"(a) : "l"(p));
    return a;
}
__device__ __forceinline__ void ldsm_x4(uint32_t addr, uint32_t* r) {
    asm volatile("ldmatrix.sync.aligned.m8n8.x4.shared.b16 {%0,%1,%2,%3}, [%4];"
        : "=r"(r[0]), "=r"(r[1]), "=r"(r[2]), "=r"(r[3]) : "r"(addr));
}
__device__ __forceinline__ void mma16816(float* d, const uint32_t* a, uint32_t b0, uint32_t b1) {
    asm volatile("mma.sync.aligned.m16n8k16.row.col.f32.f16.f16.f32 "
        "{%0,%1,%2,%3}, {%4,%5,%6,%7}, {%8,%9}, {%0,%1,%2,%3};"
        : "+f"(d[0]), "+f"(d[1]), "+f"(d[2]), "+f"(d[3])
        : "r"(a[0]), "r"(a[1]), "r"(a[2]), "r"(a[3]), "r"(b0), "r"(b1));
}
__device__ __forceinline__ uint32_t packh2(float lo, float hi) {
    uint32_t r;
    asm("cvt.rn.f16x2.f32 %0, %1, %2;" : "=r"(r) : "f"(hi), "f"(lo));
    return r;
}

// ---------------- dtype detection: int64 edge_index has zero high words ----------------
__global__ void k_detect(const unsigned int* __restrict__ w, int nwords) {
    __shared__ int nz;
    if (threadIdx.x == 0) nz = 0;
    __syncthreads();
    int lim = nwords < 4096 ? nwords : 4096;
    int any = 0;
    for (int i = 1 + 2 * (int)threadIdx.x; i < lim; i += 2 * (int)blockDim.x)
        if (w[i] != 0u) any = 1;
    if (any) atomicOr(&nz, 1);
    __syncthreads();
    if (threadIdx.x == 0) g_is64 = (nz == 0) ? 1 : 0;
}

// ---------------- zero: output accumulator + degree + histogram ----------------
__global__ void k_zero(float* __restrict__ out, int nout, int ndeg) {
    int i = blockIdx.x * blockDim.x + threadIdx.x;
    if (i < nout)                    out[i] = 0.0f;
    else if (i < nout + ndeg)        g_deg[i - nout] = 0.0f;
    else if (i < nout + ndeg + NBKT) g_hist[i - nout - ndeg] = 0;
}

// ---------------- edge preprocessing: pack descriptor + degree + bucket hist ----------------
__global__ __launch_bounds__(256)
void k_eprep(const void* __restrict__ ei, const float* __restrict__ pseudo, int E) {
    int e = blockIdx.x * blockDim.x + threadIdx.x;
    if (e >= E) return;
    int r, c;
    if (g_is64) {
        const long long* p = (const long long*)ei;
        r = (int)p[e]; c = (int)p[(size_t)E + e];
    } else {
        const int* p = (const int*)ei;
        r = p[e]; c = p[E + e];
    }
    float2 ps = ((const float2*)pseudo)[e];
    float px = ps.x * 4.0f, py = ps.y * 4.0f;   // scale = K-1 (open spline)
    float lx = fminf(fmaxf(floorf(px), 0.0f), 3.0f);
    float ly = fminf(fmaxf(floorf(py), 0.0f), 3.0f);
    int kidx = (int)ly * 5 + (int)lx;           // 0..18
    g_edesc[e] = make_uint4((uint32_t)r,
                            (uint32_t)c | ((uint32_t)kidx << 20),
                            __float_as_uint(px - lx),
                            __float_as_uint(py - ly));
    atomicAdd(&g_deg[r], 1.0f);
    atomicAdd(&g_hist[c >> 7], 1);
}

// ---------------- exclusive scan of bucket histogram (1 block, 1024 thr) ----------------
__global__ void k_scan() {
    __shared__ int s[NBKT];
    int t = threadIdx.x;
    int h = g_hist[t];
    s[t] = h;
    __syncthreads();
    for (int off = 1; off < NBKT; off <<= 1) {
        int v = (t >= off) ? s[t - off] : 0;
        __syncthreads();
        s[t] += v;
        __syncthreads();
    }
    g_off[t] = s[t] - h;   // exclusive prefix
}

// ---------------- scatter: counting-sort descriptors by col bucket ----------------
__global__ __launch_bounds__(256)
void k_scatter(int E) {
    int e = blockIdx.x * blockDim.x + threadIdx.x;
    if (e >= E) return;
    uint4 d = g_edesc[e];
    int b = (int)(d.y & 0xFFFFFu) >> 7;
    int pos = atomicAdd(&g_off[b], 1);
    g_edesc2[pos] = d;
}

// ---------------- W transpose+convert: g_Wh[p][i] = W[k,i,o], p=k*32+o ----------------
__global__ void k_prep(const float* __restrict__ w) {
    int t = blockIdx.x * blockDim.x + threadIdx.x;
    if (t >= KTOT * 1024) return;
    int p = t >> 5, i = t & 31;
    int k = p >> 5, o = p & 31;
    g_Wh[t] = __float2half(w[k * 1024 + i * 32 + o]);
}

// ---------------- Z = x @ Wt via mma.sync m16n8k16, split-N over gridDim.y ----------------
#define NB_COLS 400
#define SB_OFF  10240                    // A: 128*80
#define ZG_SMEM (10240 + NB_COLS * 80)   // + B: 400*80 = 42240

__global__ __launch_bounds__(256, 4)
void k_zgemm_mma(const float* __restrict__ x, int N) {
    extern __shared__ __align__(128) char smem[];
    char* sA = smem;
    char* sB = smem + SB_OFF;
    int tid = threadIdx.x;
    int n0 = blockIdx.x * 128;
    int colbase = blockIdx.y * NB_COLS;

    for (int g = tid; g < NB_COLS * 4; g += 256) {
        int row = g >> 2, sub = g & 3;
        *(uint4*)(sB + row * 80 + sub * 16) =
            *(const uint4*)(g_Wh + (colbase + row) * 32 + sub * 8);
    }
    for (int g = tid; g < 512; g += 256) {
        int row = g >> 2, sub = g & 3;
        int n = n0 + row;
        uint4 hv = make_uint4(0, 0, 0, 0);
        if (n < N) {
            const float4* xp = (const float4*)(x + (size_t)n * 32 + sub * 8);
            float4 a = xp[0], b = xp[1];
            hv.x = packh2(a.x, a.y);
            hv.y = packh2(a.z, a.w);
            hv.z = packh2(b.x, b.y);
            hv.w = packh2(b.z, b.w);
        }
        *(uint4*)(sA + row * 80 + sub * 16) = hv;
    }
    __syncthreads();

    int wid = tid >> 5, lane = tid & 31;
    int m0 = wid * 16;
    int r = lane & 7, sel = lane >> 3;

    uint32_t aaddr = smem_u32(sA + (m0 + r + ((sel & 1) ? 8 : 0)) * 80 + (sel >> 1) * 16);
    uint32_t a[8];
    ldsm_x4(aaddr,      a);
    ldsm_x4(aaddr + 32, a + 4);

    uint32_t sBu  = smem_u32(sB);
    uint32_t bofs = (r + ((sel >> 1) ? 8 : 0)) * 80 + (sel & 1) * 16;

    int mrow  = lane >> 2;
    int ncol0 = (lane & 3) * 2;
    int node_lo = n0 + m0 + mrow;
    int node_hi = node_lo + 8;
    __half* z_lo = g_Zh + (size_t)node_lo * KM + colbase;
    __half* z_hi = g_Zh + (size_t)node_hi * KM + colbase;
    bool ok_lo = node_lo < N, ok_hi = node_hi < N;

    for (int nb = 0; nb < NB_COLS; nb += 16) {
        uint32_t baddr = sBu + nb * 80 + bofs;
        uint32_t b[8];
        ldsm_x4(baddr,      b);
        ldsm_x4(baddr + 32, b + 4);

        float acc0[4] = {0.f, 0.f, 0.f, 0.f};
        float acc1[4] = {0.f, 0.f, 0.f, 0.f};
        mma16816(acc0, a,     b[0], b[1]);
        mma16816(acc0, a + 4, b[4], b[5]);
        mma16816(acc1, a,     b[2], b[3]);
        mma16816(acc1, a + 4, b[6], b[7]);

        if (ok_lo) {
            *(uint32_t*)(z_lo + nb + ncol0)     = packh2(acc0[0], acc0[1]);
            *(uint32_t*)(z_lo + nb + 8 + ncol0) = packh2(acc1[0], acc1[1]);
        }
        if (ok_hi) {
            *(uint32_t*)(z_hi + nb + ncol0)     = packh2(acc0[2], acc0[3]);
            *(uint32_t*)(z_hi + nb + 8 + ncol0) = packh2(acc1[2], acc1[3]);
        }
    }
}

// ---------------- edge phase: col-sorted descriptors, 6 edges/warp-iteration ----------------
#define EB 6
__global__ __launch_bounds__(256, 3)
void k_edge(float* __restrict__ out, int E) {
    int lane   = threadIdx.x & 31;
    int warp   = (blockIdx.x * blockDim.x + threadIdx.x) >> 5;
    int nwarps = (gridDim.x * blockDim.x) >> 5;

    for (int q = warp * EB; q < E; q += nwarps * EB) {
        uint4 d[EB];
#pragma unroll
        for (int j = 0; j < EB; j++) {
            int e = q + j; if (e > E - 1) e = E - 1;
            d[j] = g_edesc2[e];                      // 16B broadcast load, sequential
        }
        float z[EB][4];
#pragma unroll
        for (int j = 0; j < EB; j++) {
            uint32_t cp = d[j].y;
            const __half* zb = g_Zh + (size_t)(cp & 0xFFFFFu) * KM
                             + ((cp >> 20) << 5) + lane;
            z[j][0] = __half2float(zb[0]);     // tap (ix  , iy  )
            z[j][1] = __half2float(zb[32]);    // tap (ix+1, iy  )
            z[j][2] = __half2float(zb[160]);   // tap (ix  , iy+1)
            z[j][3] = __half2float(zb[192]);   // tap (ix+1, iy+1)
        }
#pragma unroll
        for (int j = 0; j < EB; j++) {
            if (q + j < E) {
                float fx = __uint_as_float(d[j].z);
                float fy = __uint_as_float(d[j].w);
                float v = (1.0f - fy) * ((1.0f - fx) * z[j][0] + fx * z[j][1])
                        +         fy  * ((1.0f - fx) * z[j][2] + fx * z[j][3]);
                atomicAdd(out + (size_t)d[j].x * 32 + lane, v);
            }
        }
    }
}

// ---------------- finalize: mean-divide + root term + bias ----------------
__global__ __launch_bounds__(256)
void k_final(const float* __restrict__ x, const float* __restrict__ rootw,
             const float* __restrict__ bias, float* __restrict__ out, int N) {
    __shared__ float sR[1024];
    __shared__ float sB[32];
    for (int i = threadIdx.x; i < 1024; i += blockDim.x) sR[i] = rootw[i];
    if (threadIdx.x < 32) sB[threadIdx.x] = bias[threadIdx.x];
    __syncthreads();

    int gid = blockIdx.x * blockDim.x + threadIdx.x;
    if (gid >= N * 32) return;
    int n = gid >> 5, o = gid & 31;

    float xv  = x[gid];
    float acc = 0.0f;
#pragma unroll
    for (int i = 0; i < 32; i++) {
        float xi = __shfl_sync(0xffffffffu, xv, i);
        acc += xi * sR[i * 32 + o];
    }
    float dgg = fmaxf(g_deg[n], 1.0f);
    out[gid] = out[gid] / dgg + acc + sB[o];
}

// ---------------- launch ----------------
extern "C" void kernel_launch(void* const* d_in, const int* in_sizes, int n_in,
                              void* d_out, int out_size) {
    const float* x      = (const float*)d_in[0];
    const void*  ei     = d_in[1];
    const float* pseudo = (const float*)d_in[2];
    const float* weight = (const float*)d_in[3];
    const float* rootw  = (const float*)d_in[4];
    const float* bias   = (const float*)d_in[5];
    float*       out    = (float*)d_out;

    int N = in_sizes[0] / 32;
    int E = in_sizes[2] / 2;

    k_detect<<<1, 256>>>((const unsigned int*)ei, 2 * E);

    int ztot = N * 32 + N + NBKT;
    k_zero<<<(ztot + 255) / 256, 256>>>(out, N * 32, N);

    k_eprep<<<(E + 255) / 256, 256>>>(ei, pseudo, E);
    k_scan<<<1, NBKT>>>();
    k_scatter<<<(E + 255) / 256, 256>>>(E);

    k_prep<<<(KTOT * 1024 + 255) / 256, 256>>>(weight);
    cudaFuncSetAttribute(k_zgemm_mma, cudaFuncAttributeMaxDynamicSharedMemorySize, ZG_SMEM);
    dim3 zg((N + 127) / 128, 2);
    k_zgemm_mma<<<zg, 256, ZG_SMEM>>>(x, N);

    k_edge<<<2048, 256>>>(out, E);

    k_final<<<(N * 32 + 255) / 256, 256>>>(x, rootw, bias, out, N);
}